// round 1
// baseline (speedup 1.0000x reference)
#include <cuda_runtime.h>
#include <math.h>

#define N_FFT   2048
#define HOP     512
#define NT      2880000
#define NFRAMES 5626            // 1 + NT/HOP
#define PAD     1024            // N_FFT/2
#define NCH     2

#define CHUNK   8192
#define WARM    40960

// Scratch (device globals — no allocation allowed)
__device__ float g_sigA[NCH * NT];
__device__ float g_sigB[NCH * NT];
__device__ float g_frames[NCH * NFRAMES * N_FFT];   // also reused for gain_smooth

__device__ __forceinline__ float2 cmul(float2 a, float2 b) {
    return make_float2(a.x * b.x - a.y * b.y, a.x * b.y + a.y * b.x);
}

// One block = one (channel, frame): window -> FFT(DIF) -> mask (bit-rev order) -> IFFT(DIT) -> window -> store frame
__global__ void __launch_bounds__(256)
eq_band_kernel(const float* __restrict__ x, float* __restrict__ frames,
               const float* __restrict__ gain_db_ptr, float fc)
{
    __shared__ float2 sh[N_FFT];
    __shared__ float2 tw[N_FFT / 2];

    const int tid = threadIdx.x;
    const int f = blockIdx.x;
    const int c = blockIdx.y;
    const float TWO_PI = 6.2831853071795864769f;

    // twiddles: tw[k] = exp(-2*pi*i*k/N)
    for (int k = tid; k < N_FFT / 2; k += 256) {
        float s, co;
        sincosf(-(TWO_PI / N_FFT) * (float)k, &s, &co);
        tw[k] = make_float2(co, s);
    }

    // load frame: reflect pad + hann window
    const float* xc = x + c * NT;
    for (int j = tid; j < N_FFT; j += 256) {
        int p = f * HOP + j;
        int src = p - PAD;
        if (src < 0) src = -src;
        if (src >= NT) src = 2 * NT - 2 - src;
        float w = 0.5f - 0.5f * cosf((TWO_PI / N_FFT) * (float)j);
        sh[j] = make_float2(xc[src] * w, 0.f);
    }
    __syncthreads();

    // forward FFT, DIF (natural in -> bit-reversed out)
    for (int half = N_FFT / 2; half >= 1; half >>= 1) {
        int tstep = (N_FFT / 2) / half;
        for (int b = tid; b < N_FFT / 2; b += 256) {
            int pos = b & (half - 1);
            int i0 = 2 * b - pos;
            int i1 = i0 + half;
            float2 a = sh[i0], bb = sh[i1];
            float2 s = make_float2(a.x + bb.x, a.y + bb.y);
            float2 d = make_float2(a.x - bb.x, a.y - bb.y);
            sh[i0] = s;
            sh[i1] = cmul(d, tw[pos * tstep]);
        }
        __syncthreads();
    }

    // mask in bit-reversed order; mask is real & hermitian-symmetric
    {
        float gdb = gain_db_ptr[0];
        float glin = exp10f(gdb * 0.05f);
        float gm1 = glin - 1.f;
        for (int j = tid; j < N_FFT; j += 256) {
            int bin = __brev((unsigned)j) >> 21;         // 11-bit reverse
            int kk = min(bin, N_FFT - bin);
            float fr = (float)kk * (24000.f / 1024.f);
            float r = (fr - fc) / fc;                    // q = 1
            float fac = 1.f + gm1 * expf(-r * r);
            sh[j].x *= fac;
            sh[j].y *= fac;
        }
    }
    __syncthreads();

    // inverse FFT, DIT (bit-reversed in -> natural out), conj twiddles
    for (int half = 1; half <= N_FFT / 2; half <<= 1) {
        int tstep = (N_FFT / 2) / half;
        for (int b = tid; b < N_FFT / 2; b += 256) {
            int pos = b & (half - 1);
            int i0 = 2 * b - pos;
            int i1 = i0 + half;
            float2 w = tw[pos * tstep];
            w.y = -w.y;
            float2 t = cmul(sh[i1], w);
            float2 a = sh[i0];
            sh[i0] = make_float2(a.x + t.x, a.y + t.y);
            sh[i1] = make_float2(a.x - t.x, a.y - t.y);
        }
        __syncthreads();
    }

    // synthesis window + 1/N scale, store frame
    float* fo = frames + (c * NFRAMES + f) * N_FFT;
    for (int j = tid; j < N_FFT; j += 256) {
        float w = 0.5f - 0.5f * cosf((TWO_PI / N_FFT) * (float)j);
        fo[j] = sh[j].x * w * (1.f / N_FFT);
    }
}

// overlap-add gather + window-square normalization, slice to [0, NT)
__global__ void ola_kernel(const float* __restrict__ frames, float* __restrict__ out)
{
    const float TWO_PI = 6.2831853071795864769f;
    int idx = blockIdx.x * blockDim.x + threadIdx.x;
    if (idx >= NCH * NT) return;
    int c = idx / NT;
    int t = idx - c * NT;
    int tt = t + PAD;
    int fmax = tt / HOP;            if (fmax > NFRAMES - 1) fmax = NFRAMES - 1;
    int fmin = (tt - (N_FFT - 1) + (HOP - 1)) / HOP;   if (fmin < 0) fmin = 0;
    float sum = 0.f, ws = 0.f;
    for (int f = fmin; f <= fmax; ++f) {
        int n = tt - f * HOP;
        sum += frames[(c * NFRAMES + f) * N_FFT + n];
        float w = 0.5f - 0.5f * cosf((TWO_PI / N_FFT) * (float)n);
        ws += w * w;
    }
    out[idx] = sum / (ws > 1e-11f ? ws : 1.f);
}

// gr[t] = max(20*log10(|x|+1e-8) - thr, 0) * (1 - 1/ratio)
__global__ void gr_kernel(const float* __restrict__ x, float* __restrict__ gr,
                          const float* __restrict__ thr_p, const float* __restrict__ ratio_p)
{
    int idx = blockIdx.x * blockDim.x + threadIdx.x;
    if (idx >= NCH * NT) return;
    float thr = thr_p[0];
    float ratio = ratio_p[0];
    float aa = fabsf(x[idx]) + 1e-8f;
    float adb = 20.f * log10f(aa);
    gr[idx] = fmaxf(adb - thr, 0.f) * (1.f - 1.f / ratio);
}

// chunked sequential gain follower with warm-up (contraction => warm-up error decays)
__global__ void scan_kernel(const float* __restrict__ gr, float* __restrict__ gs,
                            const float* __restrict__ att_p, const float* __restrict__ rel_p)
{
    int chunk = blockIdx.x * blockDim.x + threadIdx.x;
    int c = blockIdx.y;
    const int nchunks = (NT + CHUNK - 1) / CHUNK;
    if (chunk >= nchunks) return;
    float a_att = 1.f - expf(-1.f / (att_p[0] * 48000.f));
    float a_rel = 1.f - expf(-1.f / (rel_p[0] * 48000.f));
    const float* grc = gr + c * NT;
    float* gsc = gs + c * NT;
    int c0 = chunk * CHUNK;
    int cend = c0 + CHUNK; if (cend > NT) cend = NT;
    int s = c0 - WARM; if (s < 1) s = 1;
    float state = 0.f;
    if (c0 == 0) gsc[0] = 0.f;
    for (int t = s; t < cend; ++t) {
        float g = grc[t];
        float alpha = (g > state) ? a_att : a_rel;
        state = (1.f - alpha) * state + alpha * g;
        if (t >= c0) gsc[t] = state;
    }
}

// apply smoothed gain + makeup, then saturation
__global__ void final_kernel(const float* __restrict__ x, const float* __restrict__ gs,
                             float* __restrict__ out,
                             const float* __restrict__ makeup_p, const float* __restrict__ sat_p)
{
    int idx = blockIdx.x * blockDim.x + threadIdx.x;
    if (idx >= NCH * NT) return;
    float mk = makeup_p[0];
    float sat = sat_p[0];
    float xv = x[idx];
    float aa = fabsf(xv) + 1e-8f;
    float gl = exp10f((mk - gs[idx]) * 0.05f);
    float sgn = (xv > 0.f) ? 1.f : ((xv < 0.f) ? -1.f : 0.f);
    float y = sgn * aa * gl;
    if (sat > 1.f) y = tanhf(y * sat) / sat;
    out[idx] = y;
}

extern "C" void kernel_launch(void* const* d_in, const int* in_sizes, int n_in,
                              void* d_out, int out_size)
{
    const float* audio      = (const float*)d_in[0];
    const float* eq_low     = (const float*)d_in[1];
    const float* eq_lowmid  = (const float*)d_in[2];
    const float* eq_highmid = (const float*)d_in[3];
    const float* eq_high    = (const float*)d_in[4];
    const float* thr        = (const float*)d_in[5];
    const float* ratio      = (const float*)d_in[6];
    const float* attack     = (const float*)d_in[7];
    const float* release    = (const float*)d_in[8];
    const float* makeup     = (const float*)d_in[9];
    const float* satur      = (const float*)d_in[10];
    float* out = (float*)d_out;

    float *sigA, *sigB, *frames;
    cudaGetSymbolAddress((void**)&sigA, g_sigA);
    cudaGetSymbolAddress((void**)&sigB, g_sigB);
    cudaGetSymbolAddress((void**)&frames, g_frames);

    dim3 gEq(NFRAMES, NCH);
    const int EW = 256;
    int ewBlocks = (NCH * NT + EW - 1) / EW;

    // EQ band chain (ping-pong)
    eq_band_kernel<<<gEq, 256>>>(audio, frames, eq_low, 100.f);
    ola_kernel<<<ewBlocks, EW>>>(frames, sigA);
    eq_band_kernel<<<gEq, 256>>>(sigA, frames, eq_lowmid, 500.f);
    ola_kernel<<<ewBlocks, EW>>>(frames, sigB);
    eq_band_kernel<<<gEq, 256>>>(sigB, frames, eq_highmid, 3000.f);
    ola_kernel<<<ewBlocks, EW>>>(frames, sigA);
    eq_band_kernel<<<gEq, 256>>>(sigA, frames, eq_high, 10000.f);
    ola_kernel<<<ewBlocks, EW>>>(frames, sigB);

    // compressor
    gr_kernel<<<ewBlocks, EW>>>(sigB, sigA, thr, ratio);
    int nchunks = (NT + CHUNK - 1) / CHUNK;
    dim3 gScan((nchunks + 127) / 128, NCH);
    scan_kernel<<<gScan, 128>>>(sigA, frames, attack, release);

    // gain + saturation
    final_kernel<<<ewBlocks, EW>>>(sigB, frames, out, makeup, satur);
}

// round 2
// speedup vs baseline: 3.1343x; 3.1343x over previous
#include <cuda_runtime.h>
#include <math.h>

#define N_FFT   2048
#define HOP     512
#define NT      2880000
#define NFRAMES 5626            // 1 + NT/HOP
#define NPAIRS  2813            // NFRAMES/2
#define PAD     1024            // N_FFT/2
#define NCH     2

#define CHUNK   2048
#define WARM    20480

#define TWO_PI_F 6.2831853071795864769f

// Scratch (device globals — no allocation allowed)
__device__ float g_sigA[NCH * NT];
__device__ float g_sigB[NCH * NT];
__device__ float g_frames[NCH * NFRAMES * N_FFT];   // also reused for gain_smooth

struct C2 { float x, y; };
__device__ __forceinline__ C2 cmulC(C2 a, C2 b) { return { a.x*b.x - a.y*b.y, a.x*b.y + a.y*b.x }; }
__device__ __forceinline__ C2 caddC(C2 a, C2 b) { return { a.x + b.x, a.y + b.y }; }
__device__ __forceinline__ C2 csubC(C2 a, C2 b) { return { a.x - b.x, a.y - b.y }; }

// padded swizzle to avoid smem bank conflicts
__device__ __forceinline__ int SWZ(int p) { return p + (p >> 5); }

// 8-point DFT. SGN = -1 forward (e^{-i}), +1 inverse (unnormalized)
template<int SGN>
__device__ __forceinline__ void dft8(C2 v[8]) {
    const float r = 0.70710678118654752f;
    const float S = (float)SGN;
    // even DFT4 on v0,v2,v4,v6
    C2 a0 = caddC(v[0], v[4]), a1 = csubC(v[0], v[4]);
    C2 a2 = caddC(v[2], v[6]), a3 = csubC(v[2], v[6]);
    C2 E0 = caddC(a0, a2), E2 = csubC(a0, a2);
    C2 E1 = { a1.x - S * a3.y, a1.y + S * a3.x };
    C2 E3 = { a1.x + S * a3.y, a1.y - S * a3.x };
    // odd DFT4 on v1,v3,v5,v7
    C2 b0 = caddC(v[1], v[5]), b1 = csubC(v[1], v[5]);
    C2 b2 = caddC(v[3], v[7]), b3 = csubC(v[3], v[7]);
    C2 O0 = caddC(b0, b2), O2 = csubC(b0, b2);
    C2 O1 = { b1.x - S * b3.y, b1.y + S * b3.x };
    C2 O3 = { b1.x + S * b3.y, b1.y - S * b3.x };
    // twiddle odd outputs by w8^k, w8 = e^{S*i*pi/4}
    C2 T1 = { r * (O1.x - S * O1.y), r * (O1.y + S * O1.x) };
    C2 T2 = { -S * O2.y, S * O2.x };
    C2 T3 = { -r * (O3.x + S * O3.y), r * (S * O3.x - O3.y) };
    v[0] = caddC(E0, O0); v[4] = csubC(E0, O0);
    v[1] = caddC(E1, T1); v[5] = csubC(E1, T1);
    v[2] = caddC(E2, T2); v[6] = csubC(E2, T2);
    v[3] = caddC(E3, T3); v[7] = csubC(E3, T3);
}

// 4-point DFT, contiguous input, SGN as above
template<int SGN>
__device__ __forceinline__ void dft4(C2 u[4]) {
    const float S = (float)SGN;
    C2 a0 = caddC(u[0], u[2]), a1 = csubC(u[0], u[2]);
    C2 a2 = caddC(u[1], u[3]), a3 = csubC(u[1], u[3]);
    u[0] = caddC(a0, a2); u[2] = csubC(a0, a2);
    u[1] = { a1.x - S * a3.y, a1.y + S * a3.x };
    u[3] = { a1.x + S * a3.y, a1.y - S * a3.x };
}

// one radix-8 exchange stage. M = sub-transform length, j in [0, M/8), base = block start.
// forward (SGN=-1): DFT8 then twiddle W_M^{jk}. inverse (SGN=+1): twiddle then DFT8.
template<int SGN>
__device__ __forceinline__ void stage8(float2* sh, int M, int j, int base) {
    const int span = M >> 3;
    const int p0 = base + j;
    C2 v[8];
#pragma unroll
    for (int k = 0; k < 8; ++k) {
        float2 t = sh[SWZ(p0 + k * span)];
        v[k] = { t.x, t.y };
    }
    float sn, cs;
    sincosf(((float)SGN * TWO_PI_F) * ((float)j / (float)M), &sn, &cs);
    C2 w1 = { cs, sn };
    C2 w2 = cmulC(w1, w1), w3 = cmulC(w2, w1), w4 = cmulC(w2, w2);
    C2 w5 = cmulC(w3, w2), w6 = cmulC(w3, w3), w7 = cmulC(w4, w3);
    if (SGN < 0) {
        dft8<-1>(v);
        v[1] = cmulC(v[1], w1); v[2] = cmulC(v[2], w2); v[3] = cmulC(v[3], w3);
        v[4] = cmulC(v[4], w4); v[5] = cmulC(v[5], w5); v[6] = cmulC(v[6], w6);
        v[7] = cmulC(v[7], w7);
    } else {
        v[1] = cmulC(v[1], w1); v[2] = cmulC(v[2], w2); v[3] = cmulC(v[3], w3);
        v[4] = cmulC(v[4], w4); v[5] = cmulC(v[5], w5); v[6] = cmulC(v[6], w6);
        v[7] = cmulC(v[7], w7);
        dft8<1>(v);
    }
#pragma unroll
    for (int k = 0; k < 8; ++k)
        sh[SWZ(p0 + k * span)] = make_float2(v[k].x, v[k].y);
}

// One block = one (channel, frame-pair). Two real frames packed into one complex FFT.
// Mask is real & even => mask applied directly to packed spectrum.
__global__ void __launch_bounds__(256)
eq_pair_kernel(const float* __restrict__ x, float* __restrict__ frames,
               const float* __restrict__ gain_db_ptr, float fc)
{
    __shared__ float2 sh[N_FFT + (N_FFT >> 5)];   // 2112 float2, swizzled

    const int tid = threadIdx.x;
    const int P = blockIdx.x;
    const int c = blockIdx.y;
    const int f0 = 2 * P;

    const float* xc = x + c * NT;
    float wreg[8];

    // ---- load: reflect pad + hann window; re = frame f0, im = frame f0+1
#pragma unroll
    for (int k = 0; k < 8; ++k) {
        int j = tid + 256 * k;
        float w = 0.5f - 0.5f * cosf((TWO_PI_F / (float)N_FFT) * (float)j);
        wreg[k] = w;
        int s0 = f0 * HOP + j - PAD;
        if (s0 < 0) s0 = -s0;
        if (s0 >= NT) s0 = 2 * NT - 2 - s0;
        int s1 = (f0 + 1) * HOP + j - PAD;
        if (s1 < 0) s1 = -s1;
        if (s1 >= NT) s1 = 2 * NT - 2 - s1;
        sh[SWZ(j)] = make_float2(xc[s0] * w, xc[s1] * w);
    }
    __syncthreads();

    // ---- forward DIF: radix-8 stages (2048 -> 256 -> 32), radix-4 fused below
    stage8<-1>(sh, 2048, tid, 0);
    __syncthreads();
    stage8<-1>(sh, 256, tid & 31, (tid >> 5) << 8);
    __syncthreads();
    stage8<-1>(sh, 32, tid >> 6, (tid & 63) << 5);
    __syncthreads();

    // ---- fused: forward radix-4 + mask (digit-reversed bins) + inverse radix-4, in registers
    {
        float gdb = gain_db_ptr[0];
        float gm1 = exp10f(gdb * 0.05f) - 1.f;
        float inv_fc = 1.f / fc;
#pragma unroll
        for (int h = 0; h < 2; ++h) {
            int base = 8 * tid + 4 * h;
            C2 u[4];
#pragma unroll
            for (int i = 0; i < 4; ++i) {
                float2 t = sh[SWZ(base + i)];
                u[i] = { t.x, t.y };
            }
            dft4<-1>(u);
            // bin index from storage digits: p = d1*256 + d2*32 + d3*4 + i
            int d1 = (base >> 8) & 7, d2 = (base >> 5) & 7, d3 = (base >> 2) & 7;
            int kbase = d1 + (d2 << 3) + (d3 << 6);
#pragma unroll
            for (int i = 0; i < 4; ++i) {
                int kk = kbase + (i << 9);
                int ks = min(kk, N_FFT - kk);
                float fr = (float)ks * (24000.f / 1024.f);
                float rr = (fr - fc) * inv_fc;    // q = 1
                float fac = 1.f + gm1 * expf(-rr * rr);
                u[i].x *= fac; u[i].y *= fac;
            }
            dft4<1>(u);
#pragma unroll
            for (int i = 0; i < 4; ++i)
                sh[SWZ(base + i)] = make_float2(u[i].x, u[i].y);
        }
    }
    __syncthreads();

    // ---- inverse DIT: undo stages in reverse order, conjugated
    stage8<1>(sh, 32, tid >> 6, (tid & 63) << 5);
    __syncthreads();
    stage8<1>(sh, 256, tid & 31, (tid >> 5) << 8);
    __syncthreads();
    stage8<1>(sh, 2048, tid, 0);
    __syncthreads();

    // ---- synthesis window + 1/N; re -> frame f0, im -> frame f0+1
    float* fo0 = frames + (c * NFRAMES + f0) * N_FFT;
    float* fo1 = fo0 + N_FFT;
#pragma unroll
    for (int k = 0; k < 8; ++k) {
        int j = tid + 256 * k;
        float2 t = sh[SWZ(j)];
        float s = wreg[k] * (1.f / (float)N_FFT);
        fo0[j] = t.x * s;
        fo1[j] = t.y * s;
    }
}

// overlap-add gather + window-square normalization, slice to [0, NT)
__global__ void ola_kernel(const float* __restrict__ frames, float* __restrict__ out)
{
    int idx = blockIdx.x * blockDim.x + threadIdx.x;
    if (idx >= NCH * NT) return;
    int c = idx / NT;
    int t = idx - c * NT;
    int tt = t + PAD;
    int fmax = tt / HOP;                               if (fmax > NFRAMES - 1) fmax = NFRAMES - 1;
    int fmin = (tt - (N_FFT - 1) + (HOP - 1)) / HOP;   if (fmin < 0) fmin = 0;
    float sum = 0.f, ws = 0.f;
    for (int f = fmin; f <= fmax; ++f) {
        int n = tt - f * HOP;
        sum += frames[(c * NFRAMES + f) * N_FFT + n];
        float w = 0.5f - 0.5f * cosf((TWO_PI_F / (float)N_FFT) * (float)n);
        ws += w * w;
    }
    out[idx] = sum / (ws > 1e-11f ? ws : 1.f);
}

// gr[t] = max(20*log10(|x|+1e-8) - thr, 0) * (1 - 1/ratio)
__global__ void gr_kernel(const float* __restrict__ x, float* __restrict__ gr,
                          const float* __restrict__ thr_p, const float* __restrict__ ratio_p)
{
    int idx = blockIdx.x * blockDim.x + threadIdx.x;
    if (idx >= NCH * NT) return;
    float thr = thr_p[0];
    float ratio = ratio_p[0];
    float aa = fabsf(x[idx]) + 1e-8f;
    float adb = 20.f * log10f(aa);
    gr[idx] = fmaxf(adb - thr, 0.f) * (1.f - 1.f / ratio);
}

// chunked sequential gain follower with warm-up (contraction => warm-up error decays)
__global__ void scan_kernel(const float* __restrict__ gr, float* __restrict__ gs,
                            const float* __restrict__ att_p, const float* __restrict__ rel_p)
{
    int chunk = blockIdx.x * blockDim.x + threadIdx.x;
    int c = blockIdx.y;
    const int nchunks = (NT + CHUNK - 1) / CHUNK;
    if (chunk >= nchunks) return;
    float a_att = 1.f - expf(-1.f / (att_p[0] * 48000.f));
    float a_rel = 1.f - expf(-1.f / (rel_p[0] * 48000.f));
    const float* grc = gr + c * NT;
    float* gsc = gs + c * NT;
    int c0 = chunk * CHUNK;
    int cend = c0 + CHUNK; if (cend > NT) cend = NT;
    int s = c0 - WARM; if (s < 1) s = 1;
    float state = 0.f;
    if (c0 == 0) gsc[0] = 0.f;
    for (int t = s; t < cend; ++t) {
        float g = grc[t];
        float d = g - state;
        float alpha = (d > 0.f) ? a_att : a_rel;
        state = fmaf(alpha, d, state);
        if (t >= c0) gsc[t] = state;
    }
}

// apply smoothed gain + makeup, then saturation
__global__ void final_kernel(const float* __restrict__ x, const float* __restrict__ gs,
                             float* __restrict__ out,
                             const float* __restrict__ makeup_p, const float* __restrict__ sat_p)
{
    int idx = blockIdx.x * blockDim.x + threadIdx.x;
    if (idx >= NCH * NT) return;
    float mk = makeup_p[0];
    float sat = sat_p[0];
    float xv = x[idx];
    float aa = fabsf(xv) + 1e-8f;
    float gl = exp10f((mk - gs[idx]) * 0.05f);
    float sgn = (xv > 0.f) ? 1.f : ((xv < 0.f) ? -1.f : 0.f);
    float y = sgn * aa * gl;
    if (sat > 1.f) y = tanhf(y * sat) / sat;
    out[idx] = y;
}

extern "C" void kernel_launch(void* const* d_in, const int* in_sizes, int n_in,
                              void* d_out, int out_size)
{
    const float* audio      = (const float*)d_in[0];
    const float* eq_low     = (const float*)d_in[1];
    const float* eq_lowmid  = (const float*)d_in[2];
    const float* eq_highmid = (const float*)d_in[3];
    const float* eq_high    = (const float*)d_in[4];
    const float* thr        = (const float*)d_in[5];
    const float* ratio      = (const float*)d_in[6];
    const float* attack     = (const float*)d_in[7];
    const float* release    = (const float*)d_in[8];
    const float* makeup     = (const float*)d_in[9];
    const float* satur      = (const float*)d_in[10];
    float* out = (float*)d_out;

    float *sigA, *sigB, *frames;
    cudaGetSymbolAddress((void**)&sigA, g_sigA);
    cudaGetSymbolAddress((void**)&sigB, g_sigB);
    cudaGetSymbolAddress((void**)&frames, g_frames);

    dim3 gEq(NPAIRS, NCH);
    const int EW = 256;
    int ewBlocks = (NCH * NT + EW - 1) / EW;

    // EQ band chain (ping-pong)
    eq_pair_kernel<<<gEq, 256>>>(audio, frames, eq_low, 100.f);
    ola_kernel<<<ewBlocks, EW>>>(frames, sigA);
    eq_pair_kernel<<<gEq, 256>>>(sigA, frames, eq_lowmid, 500.f);
    ola_kernel<<<ewBlocks, EW>>>(frames, sigB);
    eq_pair_kernel<<<gEq, 256>>>(sigB, frames, eq_highmid, 3000.f);
    ola_kernel<<<ewBlocks, EW>>>(frames, sigA);
    eq_pair_kernel<<<gEq, 256>>>(sigA, frames, eq_high, 10000.f);
    ola_kernel<<<ewBlocks, EW>>>(frames, sigB);

    // compressor
    gr_kernel<<<ewBlocks, EW>>>(sigB, sigA, thr, ratio);
    int nchunks = (NT + CHUNK - 1) / CHUNK;
    dim3 gScan((nchunks + 127) / 128, NCH);
    scan_kernel<<<gScan, 128>>>(sigA, frames, attack, release);

    // gain + saturation
    final_kernel<<<ewBlocks, EW>>>(sigB, frames, out, makeup, satur);
}

// round 3
// speedup vs baseline: 4.1594x; 1.3271x over previous
#include <cuda_runtime.h>
#include <math.h>

#define N_FFT   2048
#define HOP     512
#define NT      2880000
#define NFRAMES 5626            // 1 + NT/HOP
#define NPAIRS  2813            // NFRAMES/2
#define PAD     1024            // N_FFT/2
#define NCH     2

#define CHUNK   2048
#define WARM    16384

#define TWO_PI_F 6.2831853071795864769f
#define LN10_F   2.3025850929940457f

// Scratch (device globals — no allocation allowed)
__device__ float g_sigA[NCH * NT];
__device__ float g_sigB[NCH * NT];
__device__ float g_frames[NCH * NFRAMES * N_FFT];   // also reused for gain_smooth

struct C2 { float x, y; };
__device__ __forceinline__ C2 cmulC(C2 a, C2 b) { return { a.x*b.x - a.y*b.y, a.x*b.y + a.y*b.x }; }
__device__ __forceinline__ C2 caddC(C2 a, C2 b) { return { a.x + b.x, a.y + b.y }; }
__device__ __forceinline__ C2 csubC(C2 a, C2 b) { return { a.x - b.x, a.y - b.y }; }

// padded swizzle to avoid smem bank conflicts
__device__ __forceinline__ int SWZ(int p) { return p + (p >> 5); }

// 8-point DFT. SGN = -1 forward (e^{-i}), +1 inverse (unnormalized)
template<int SGN>
__device__ __forceinline__ void dft8(C2 v[8]) {
    const float r = 0.70710678118654752f;
    const float S = (float)SGN;
    C2 a0 = caddC(v[0], v[4]), a1 = csubC(v[0], v[4]);
    C2 a2 = caddC(v[2], v[6]), a3 = csubC(v[2], v[6]);
    C2 E0 = caddC(a0, a2), E2 = csubC(a0, a2);
    C2 E1 = { a1.x - S * a3.y, a1.y + S * a3.x };
    C2 E3 = { a1.x + S * a3.y, a1.y - S * a3.x };
    C2 b0 = caddC(v[1], v[5]), b1 = csubC(v[1], v[5]);
    C2 b2 = caddC(v[3], v[7]), b3 = csubC(v[3], v[7]);
    C2 O0 = caddC(b0, b2), O2 = csubC(b0, b2);
    C2 O1 = { b1.x - S * b3.y, b1.y + S * b3.x };
    C2 O3 = { b1.x + S * b3.y, b1.y - S * b3.x };
    C2 T1 = { r * (O1.x - S * O1.y), r * (O1.y + S * O1.x) };
    C2 T2 = { -S * O2.y, S * O2.x };
    C2 T3 = { -r * (O3.x + S * O3.y), r * (S * O3.x - O3.y) };
    v[0] = caddC(E0, O0); v[4] = csubC(E0, O0);
    v[1] = caddC(E1, T1); v[5] = csubC(E1, T1);
    v[2] = caddC(E2, T2); v[6] = csubC(E2, T2);
    v[3] = caddC(E3, T3); v[7] = csubC(E3, T3);
}

template<int SGN>
__device__ __forceinline__ void dft4(C2 u[4]) {
    const float S = (float)SGN;
    C2 a0 = caddC(u[0], u[2]), a1 = csubC(u[0], u[2]);
    C2 a2 = caddC(u[1], u[3]), a3 = csubC(u[1], u[3]);
    u[0] = caddC(a0, a2); u[2] = csubC(a0, a2);
    u[1] = { a1.x - S * a3.y, a1.y + S * a3.x };
    u[3] = { a1.x + S * a3.y, a1.y - S * a3.x };
}

// one radix-8 exchange stage. M = sub-transform length, j in [0, M/8), base = block start.
template<int SGN>
__device__ __forceinline__ void stage8(float2* sh, int M, int j, int base) {
    const int span = M >> 3;
    const int p0 = base + j;
    C2 v[8];
#pragma unroll
    for (int k = 0; k < 8; ++k) {
        float2 t = sh[SWZ(p0 + k * span)];
        v[k] = { t.x, t.y };
    }
    float sn, cs;
    __sincosf(((float)SGN * TWO_PI_F) * ((float)j / (float)M), &sn, &cs);
    C2 w1 = { cs, sn };
    C2 w2 = cmulC(w1, w1), w3 = cmulC(w2, w1), w4 = cmulC(w2, w2);
    C2 w5 = cmulC(w3, w2), w6 = cmulC(w3, w3), w7 = cmulC(w4, w3);
    if (SGN < 0) {
        dft8<-1>(v);
        v[1] = cmulC(v[1], w1); v[2] = cmulC(v[2], w2); v[3] = cmulC(v[3], w3);
        v[4] = cmulC(v[4], w4); v[5] = cmulC(v[5], w5); v[6] = cmulC(v[6], w6);
        v[7] = cmulC(v[7], w7);
    } else {
        v[1] = cmulC(v[1], w1); v[2] = cmulC(v[2], w2); v[3] = cmulC(v[3], w3);
        v[4] = cmulC(v[4], w4); v[5] = cmulC(v[5], w5); v[6] = cmulC(v[6], w6);
        v[7] = cmulC(v[7], w7);
        dft8<1>(v);
    }
#pragma unroll
    for (int k = 0; k < 8; ++k)
        sh[SWZ(p0 + k * span)] = make_float2(v[k].x, v[k].y);
}

// One block = one (channel, frame-pair). Two real frames packed into one complex FFT.
__global__ void __launch_bounds__(256)
eq_pair_kernel(const float* __restrict__ x, float* __restrict__ frames,
               const float* __restrict__ gain_db_ptr, float fc)
{
    __shared__ float2 sh[N_FFT + (N_FFT >> 5)];   // swizzled

    const int tid = threadIdx.x;
    const int P = blockIdx.x;
    const int c = blockIdx.y;
    const int f0 = 2 * P;

    const float* xc = x + c * NT;
    float wreg[8];

    // ---- load: reflect pad + hann window; re = frame f0, im = frame f0+1
#pragma unroll
    for (int k = 0; k < 8; ++k) {
        int j = tid + 256 * k;
        float w = 0.5f - 0.5f * __cosf((TWO_PI_F / (float)N_FFT) * (float)j);
        wreg[k] = w;
        int s0 = f0 * HOP + j - PAD;
        if (s0 < 0) s0 = -s0;
        if (s0 >= NT) s0 = 2 * NT - 2 - s0;
        int s1 = (f0 + 1) * HOP + j - PAD;
        if (s1 < 0) s1 = -s1;
        if (s1 >= NT) s1 = 2 * NT - 2 - s1;
        sh[SWZ(j)] = make_float2(xc[s0] * w, xc[s1] * w);
    }
    __syncthreads();

    // ---- forward DIF: radix-8 stages (2048 -> 256 -> 32)
    stage8<-1>(sh, 2048, tid, 0);
    __syncthreads();
    stage8<-1>(sh, 256, tid & 31, (tid >> 5) << 8);
    __syncthreads();
    stage8<-1>(sh, 32, tid >> 6, (tid & 63) << 5);
    __syncthreads();

    // ---- fused: forward radix-4 + real/even mask (digit-reversed bins) + inverse radix-4
    {
        float gdb = gain_db_ptr[0];
        float gm1 = __expf(gdb * 0.05f * LN10_F) - 1.f;
        float inv_fc = 1.f / fc;
#pragma unroll
        for (int h = 0; h < 2; ++h) {
            int base = 8 * tid + 4 * h;
            C2 u[4];
#pragma unroll
            for (int i = 0; i < 4; ++i) {
                float2 t = sh[SWZ(base + i)];
                u[i] = { t.x, t.y };
            }
            dft4<-1>(u);
            int d1 = (base >> 8) & 7, d2 = (base >> 5) & 7, d3 = (base >> 2) & 7;
            int kbase = d1 + (d2 << 3) + (d3 << 6);
#pragma unroll
            for (int i = 0; i < 4; ++i) {
                int kk = kbase + (i << 9);
                int ks = min(kk, N_FFT - kk);
                float fr = (float)ks * (24000.f / 1024.f);
                float rr = (fr - fc) * inv_fc;    // q = 1
                float fac = 1.f + gm1 * __expf(-rr * rr);
                u[i].x *= fac; u[i].y *= fac;
            }
            dft4<1>(u);
#pragma unroll
            for (int i = 0; i < 4; ++i)
                sh[SWZ(base + i)] = make_float2(u[i].x, u[i].y);
        }
    }
    __syncthreads();

    // ---- inverse DIT
    stage8<1>(sh, 32, tid >> 6, (tid & 63) << 5);
    __syncthreads();
    stage8<1>(sh, 256, tid & 31, (tid >> 5) << 8);
    __syncthreads();
    stage8<1>(sh, 2048, tid, 0);
    __syncthreads();

    // ---- synthesis window + 1/N
    float* fo0 = frames + (c * NFRAMES + f0) * N_FFT;
    float* fo1 = fo0 + N_FFT;
#pragma unroll
    for (int k = 0; k < 8; ++k) {
        int j = tid + 256 * k;
        float2 t = sh[SWZ(j)];
        float s = wreg[k] * (1.f / (float)N_FFT);
        fo0[j] = t.x * s;
        fo1[j] = t.y * s;
    }
}

__device__ __forceinline__ float ola_at(const float* __restrict__ frames, int c, int t)
{
    int tt = t + PAD;
    int fmax = tt / HOP;                               if (fmax > NFRAMES - 1) fmax = NFRAMES - 1;
    int fmin = (tt - (N_FFT - 1) + (HOP - 1)) / HOP;   if (fmin < 0) fmin = 0;
    float sum = 0.f, ws = 0.f;
    for (int f = fmin; f <= fmax; ++f) {
        int n = tt - f * HOP;
        sum += frames[(c * NFRAMES + f) * N_FFT + n];
        float w = 0.5f - 0.5f * __cosf((TWO_PI_F / (float)N_FFT) * (float)n);
        ws += w * w;
    }
    return sum / (ws > 1e-11f ? ws : 1.f);
}

// overlap-add gather + window-square normalization
__global__ void ola_kernel(const float* __restrict__ frames, float* __restrict__ out)
{
    int idx = blockIdx.x * blockDim.x + threadIdx.x;
    if (idx >= NCH * NT) return;
    int c = idx / NT;
    int t = idx - c * NT;
    out[idx] = ola_at(frames, c, t);
}

// final OLA fused with gain-reduction computation
__global__ void ola_gr_kernel(const float* __restrict__ frames, float* __restrict__ out,
                              float* __restrict__ gr,
                              const float* __restrict__ thr_p, const float* __restrict__ ratio_p)
{
    int idx = blockIdx.x * blockDim.x + threadIdx.x;
    if (idx >= NCH * NT) return;
    int c = idx / NT;
    int t = idx - c * NT;
    float v = ola_at(frames, c, t);
    out[idx] = v;
    float thr = thr_p[0];
    float ratio = ratio_p[0];
    float aa = fabsf(v) + 1e-8f;
    float adb = 20.f * __log10f(aa);
    gr[idx] = fmaxf(adb - thr, 0.f) * (1.f - 1.f / ratio);
}

// chunked sequential gain follower with warm-up.
// Exact reformulation: a_att > a_rel  =>  state' = max(state+(g-state)a_att, state+(g-state)a_rel)
__global__ void scan_kernel(const float* __restrict__ gr, float* __restrict__ gs,
                            const float* __restrict__ att_p, const float* __restrict__ rel_p)
{
    int chunk = blockIdx.x * blockDim.x + threadIdx.x;
    int c = blockIdx.y;
    const int nchunks = (NT + CHUNK - 1) / CHUNK;
    if (chunk >= nchunks) return;
    float a_att = 1.f - __expf(-1.f / (att_p[0] * 48000.f));
    float a_rel = 1.f - __expf(-1.f / (rel_p[0] * 48000.f));
    float m_att = 1.f - a_att, m_rel = 1.f - a_rel;
    const float* grc = gr + c * NT;
    float* gsc = gs + c * NT;
    int c0 = chunk * CHUNK;
    int cend = c0 + CHUNK; if (cend > NT) cend = NT;
    int s = c0 - WARM; if (s < 1) s = 1;
    float state = 0.f;
    if (c0 == 0) gsc[0] = 0.f;
    // warm-up (no stores)
#pragma unroll 4
    for (int t = s; t < c0; ++t) {
        float g = grc[t];
        state = fmaxf(fmaf(m_att, state, a_att * g), fmaf(m_rel, state, a_rel * g));
    }
#pragma unroll 4
    for (int t = c0 < 1 ? 1 : c0; t < cend; ++t) {
        float g = grc[t];
        state = fmaxf(fmaf(m_att, state, a_att * g), fmaf(m_rel, state, a_rel * g));
        gsc[t] = state;
    }
}

// apply smoothed gain + makeup, then saturation (tanh via fast exp)
__global__ void final_kernel(const float* __restrict__ x, const float* __restrict__ gs,
                             float* __restrict__ out,
                             const float* __restrict__ makeup_p, const float* __restrict__ sat_p)
{
    int idx = blockIdx.x * blockDim.x + threadIdx.x;
    if (idx >= NCH * NT) return;
    float mk = makeup_p[0];
    float sat = sat_p[0];
    float xv = x[idx];
    float aa = fabsf(xv) + 1e-8f;
    float gl = __expf((mk - gs[idx]) * 0.05f * LN10_F);
    float sgn = (xv > 0.f) ? 1.f : ((xv < 0.f) ? -1.f : 0.f);
    float y = sgn * aa * gl;
    if (sat > 1.f) {
        float z = y * sat;
        float e = __expf(2.f * z);
        y = ((e - 1.f) / (e + 1.f)) / sat;
    }
    out[idx] = y;
}

extern "C" void kernel_launch(void* const* d_in, const int* in_sizes, int n_in,
                              void* d_out, int out_size)
{
    const float* audio      = (const float*)d_in[0];
    const float* eq_low     = (const float*)d_in[1];
    const float* eq_lowmid  = (const float*)d_in[2];
    const float* eq_highmid = (const float*)d_in[3];
    const float* eq_high    = (const float*)d_in[4];
    const float* thr        = (const float*)d_in[5];
    const float* ratio      = (const float*)d_in[6];
    const float* attack     = (const float*)d_in[7];
    const float* release    = (const float*)d_in[8];
    const float* makeup     = (const float*)d_in[9];
    const float* satur      = (const float*)d_in[10];
    float* out = (float*)d_out;

    float *sigA, *sigB, *frames;
    cudaGetSymbolAddress((void**)&sigA, g_sigA);
    cudaGetSymbolAddress((void**)&sigB, g_sigB);
    cudaGetSymbolAddress((void**)&frames, g_frames);

    dim3 gEq(NPAIRS, NCH);
    const int EW = 256;
    int ewBlocks = (NCH * NT + EW - 1) / EW;

    // EQ band chain (ping-pong)
    eq_pair_kernel<<<gEq, 256>>>(audio, frames, eq_low, 100.f);
    ola_kernel<<<ewBlocks, EW>>>(frames, sigA);
    eq_pair_kernel<<<gEq, 256>>>(sigA, frames, eq_lowmid, 500.f);
    ola_kernel<<<ewBlocks, EW>>>(frames, sigB);
    eq_pair_kernel<<<gEq, 256>>>(sigB, frames, eq_highmid, 3000.f);
    ola_kernel<<<ewBlocks, EW>>>(frames, sigA);
    eq_pair_kernel<<<gEq, 256>>>(sigA, frames, eq_high, 10000.f);
    // band 4 OLA fused with gain-reduction: audio -> sigB, gr -> sigA
    ola_gr_kernel<<<ewBlocks, EW>>>(frames, sigB, sigA, thr, ratio);

    // compressor envelope
    int nchunks = (NT + CHUNK - 1) / CHUNK;
    dim3 gScan((nchunks + 127) / 128, NCH);
    scan_kernel<<<gScan, 128>>>(sigA, frames, attack, release);

    // gain + saturation
    final_kernel<<<ewBlocks, EW>>>(sigB, frames, out, makeup, satur);
}